// round 16
// baseline (speedup 1.0000x reference)
#include <cuda_runtime.h>
#include <cuda_fp16.h>
#include <math.h>
#include <stdint.h>

#define LAYERS 12
#define BB 8
#define SS 512
#define HH 768
#define NHD 12
#define DHD 64
#define FFD 3072
#define M_TOK (BB*SS)   // 4096
#define QKVS 2304
#define KOFF 768
#define VOFF 1536
#define LOG2E 1.4426950408889634f

// ---------------- scratch -----------------------------------------------------
__device__ float  g_h[M_TOK*HH];
__device__ __half g_qkv[M_TOK*QKVS];
__device__ __half g_vT[BB*NHD*DHD*SS];      // [bh*64+d][s], s pair-permuted
__device__ __half g_ctx[M_TOK*HH];
__device__ float  g_attn[M_TOK*HH];
__device__ float  g_tmp[M_TOK*HH];
__device__ __half g_round[M_TOK*HH];
__device__ __half g_inter[M_TOK*FFD];

__device__ __half g_wqkvT[LAYERS*QKVS*HH];
__device__ float  g_bqkv [LAYERS*QKVS];
__device__ __half g_woT  [LAYERS*HH*HH];
__device__ __half g_wiT  [LAYERS*HH*FFD];
__device__ __half g_wo2T [LAYERS*FFD*HH];

// ---------------- helpers -----------------------------------------------------
__inline__ __device__ float warpSum(float v){
    #pragma unroll
    for(int o=16;o;o>>=1) v += __shfl_xor_sync(0xffffffffu, v, o);
    return v;
}
__device__ __forceinline__ float gelu_exact(float x){
    return 0.5f * x * (1.0f + erff(x * 0.70710678118654752440f));
}
__device__ __forceinline__ uint32_t s2u(const void* p){
    uint32_t a;
    asm("{ .reg .u64 t; cvta.to.shared.u64 t, %1; cvt.u32.u64 %0, t; }" : "=r"(a) : "l"(p));
    return a;
}
__device__ __forceinline__ int permk(int j){ return ((j&3)<<1) | (j>>2); }
__device__ __forceinline__ uint32_t h2u(__half2 h){ return *(uint32_t*)&h; }
__device__ __forceinline__ float ex2(float x){
    float r; asm("ex2.approx.f32 %0, %1;" : "=f"(r) : "f"(x)); return r;
}

#define CP_ASYNC16(dst, src) \
    asm volatile("cp.async.cg.shared.global [%0], [%1], 16;" :: "r"(dst), "l"(src))
#define CP_COMMIT() asm volatile("cp.async.commit_group;")
#define CP_WAIT(N)  asm volatile("cp.async.wait_group %0;" :: "n"(N) : "memory")

// fp16 mma, fp32 accumulate
__device__ __forceinline__ void mma_f16(float* d, const uint32_t* a, const uint32_t* b){
    asm volatile(
        "mma.sync.aligned.m16n8k16.row.col.f32.f16.f16.f32 "
        "{%0,%1,%2,%3}, {%4,%5,%6,%7}, {%8,%9}, {%0,%1,%2,%3};"
        : "+f"(d[0]), "+f"(d[1]), "+f"(d[2]), "+f"(d[3])
        : "r"(a[0]), "r"(a[1]), "r"(a[2]), "r"(a[3]), "r"(b[0]), "r"(b[1]));
}

// ---------------- elementwise ---------------------------------------------------
__global__ void round_perm_h(__half* __restrict__ dst, const float* __restrict__ src, int nPairs){
    int i = blockIdx.x*blockDim.x + threadIdx.x;
    if(i < nPairs){
        int grp = i >> 3, q = i & 7;
        ((__half2*)dst)[grp*8 + permk(q)] = __floats2half2_rn(src[2*i], src[2*i+1]);
    }
}
__global__ void concat_bias(const float* __restrict__ bq, const float* __restrict__ bk,
                            const float* __restrict__ bv, float* __restrict__ bqkv){
    int i = blockIdx.x*blockDim.x + threadIdx.x;
    if(i < LAYERS*HH){
        int l = i / HH, c = i % HH;
        bqkv[(size_t)l*QKVS + c]        = bq[i];
        bqkv[(size_t)l*QKVS + KOFF + c] = bk[i];
        bqkv[(size_t)l*QKVS + VOFF + c] = bv[i];
    }
}

// ---- transpose + rn-half + pair-perm: src [K][N] float -> dst [rowOff+n][K] half
__device__ __forceinline__ void trans_tile(
    const float* __restrict__ src, __half* __restrict__ dst,
    int K, int N, int rowOff, int n0, int k0)
{
    __shared__ float ts[32][33];
    const int t = threadIdx.x;                 // 256
    {
        const int r = t >> 3, c4 = t & 7;
        float4 v = *(const float4*)(src + (size_t)(k0+r)*N + n0 + c4*4);
        ts[r][c4*4+0] = v.x; ts[r][c4*4+1] = v.y;
        ts[r][c4*4+2] = v.z; ts[r][c4*4+3] = v.w;
    }
    __syncthreads();
    if(t < 128){
        const int nr  = t >> 2;
        const int grp = (t >> 1) & 1;
        const int h8  = t & 1;
        __align__(16) __half tmp[8];
        #pragma unroll
        for(int i=0;i<4;i++){
            const int s = h8*4 + i;
            const int q = ((s & 1) << 2) | (s >> 1);  // inverse of permk
            tmp[2*i]   = __float2half_rn(ts[grp*16 + 2*q    ][nr]);
            tmp[2*i+1] = __float2half_rn(ts[grp*16 + 2*q + 1][nr]);
        }
        *(uint4*)(dst + (size_t)(rowOff + n0 + nr)*K + k0 + grp*16 + h8*8)
            = *(uint4*)tmp;
    }
}

__global__ void trans_qkv(const float* __restrict__ Wq, const float* __restrict__ Wk,
                          const float* __restrict__ Wv, __half* __restrict__ wqkvT){
    const int z = blockIdx.z, l = z / 3, w = z % 3;
    const float* src = (w==0) ? Wq : (w==1) ? Wk : Wv;
    trans_tile(src + (size_t)l*HH*HH, wqkvT + (size_t)l*QKVS*HH,
               HH, HH, w*KOFF, blockIdx.x*32, blockIdx.y*32);
}
__global__ void trans_wo(const float* __restrict__ Wo, __half* __restrict__ woT){
    trans_tile(Wo + (size_t)blockIdx.z*HH*HH, woT + (size_t)blockIdx.z*HH*HH,
               HH, HH, 0, blockIdx.x*32, blockIdx.y*32);
}
__global__ void trans_wi(const float* __restrict__ Wi, __half* __restrict__ wiT){
    trans_tile(Wi + (size_t)blockIdx.z*HH*FFD, wiT + (size_t)blockIdx.z*HH*FFD,
               HH, FFD, 0, blockIdx.x*32, blockIdx.y*32);
}
__global__ void trans_wo2(const float* __restrict__ Wo2, __half* __restrict__ wo2T){
    trans_tile(Wo2 + (size_t)blockIdx.z*FFD*HH, wo2T + (size_t)blockIdx.z*FFD*HH,
               FFD, HH, 0, blockIdx.x*32, blockIdx.y*32);
}

// ---------------- FP16 GEMM, 128x128 tile, BK=64, 3-stage, 2 CTA/SM --------------
// MODE 0: plain +bias fp32 out (Wo, FF2). MODE 1: gelu + half pair-perm (FF1).
// MODE 2: QKV epilogue (half qkv + vT).
#define BKH 64
#define GSTAGES 3
#define SM128 (GSTAGES*(128+128)*BKH*2)    // 98304 -> 2 CTA/SM

template<int MODE>
__global__ __launch_bounds__(256, 2)
void mma_gemm(const __half* __restrict__ A, const __half* __restrict__ Wt,
              const float* __restrict__ bias, __half* __restrict__ Ch,
              float* __restrict__ Cf, __half* __restrict__ vT, int N, int K)
{
    extern __shared__ __half smh[];
    __half* Asm = smh;
    __half* Wsm = smh + GSTAGES*128*BKH;

    const int tid  = threadIdx.x;
    const int wid  = tid >> 5;
    const int lane = tid & 31;
    const int m0 = blockIdx.y * 128;
    const int n0 = blockIdx.x * 128;
    const int wm = (wid >> 1) * 32;
    const int wn = (wid & 1) * 64;
    const int g  = lane >> 2;
    const int t4 = lane & 3;
    const int xrh = (g & 3) << 4;
    const int KT = K / BKH;

    const __half* Ag = A  + (size_t)m0 * K;
    const __half* Wg = Wt + (size_t)n0 * K;

    auto load_tile = [&](int t){
        const int s = t % GSTAGES;
        __half* as = Asm + s*128*BKH;
        __half* ws = Wsm + s*128*BKH;
        #pragma unroll
        for(int l=0;l<4;l++){
            const int c = tid + l*256;
            const int row = c >> 3, k4 = c & 7;
            const int off = (k4*8) ^ ((row & 3) << 4);
            CP_ASYNC16(s2u(as + row*BKH + off), Ag + (size_t)row*K + t*BKH + k4*8);
        }
        #pragma unroll
        for(int l=0;l<4;l++){
            const int c = tid + l*256;
            const int row = c >> 3, k4 = c & 7;
            const int off = (k4*8) ^ ((row & 3) << 4);
            CP_ASYNC16(s2u(ws + row*BKH + off), Wg + (size_t)row*K + t*BKH + k4*8);
        }
        CP_COMMIT();
    };

    float acc[2][8][4];
    #pragma unroll
    for(int mi=0;mi<2;mi++)
        #pragma unroll
        for(int ni=0;ni<8;ni++)
            #pragma unroll
            for(int r=0;r<4;r++) acc[mi][ni][r] = 0.f;

    load_tile(0);
    load_tile(1);

    for(int t=0; t<KT; t++){
        if (t == KT-1) CP_WAIT(0); else CP_WAIT(1);
        __syncthreads();
        if (t+2 < KT) load_tile(t+2);

        const __half* as = Asm + (t % GSTAGES)*128*BKH;
        const __half* ws = Wsm + (t % GSTAGES)*128*BKH;

        #pragma unroll
        for(int ks=0; ks<BKH/16; ks++){
            const int kw = (ks*16) ^ xrh;
            uint32_t a[2][4], b[8][2];
            #pragma unroll
            for(int mi=0; mi<2; mi++){
                const __half* ap = as + (wm + mi*16 + g)*BKH + kw + t4*4;
                uint2 lo = *(const uint2*)ap;
                uint2 hi = *(const uint2*)(ap + 8*BKH);
                a[mi][0] = lo.x; a[mi][2] = lo.y;
                a[mi][1] = hi.x; a[mi][3] = hi.y;
            }
            #pragma unroll
            for(int ni=0; ni<8; ni++){
                uint2 bv = *(const uint2*)(ws + (wn + ni*8 + g)*BKH + kw + t4*4);
                b[ni][0] = bv.x; b[ni][1] = bv.y;
            }
            #pragma unroll
            for(int mi=0; mi<2; mi++)
                #pragma unroll
                for(int ni=0; ni<8; ni++)
                    mma_f16(acc[mi][ni], a[mi], b[ni]);
        }
    }

    if (MODE == 0){
        // plain +bias, fp32 staged [128][132], coalesced float4 stores
        __syncthreads();
        float* stage = (float*)smh;     // 128*132*4 = 67584 B
        #pragma unroll
        for(int mi=0; mi<2; mi++){
            #pragma unroll
            for(int ni=0; ni<8; ni++){
                const int col = wn + ni*8 + 2*t4;
                const float bx = bias[n0+col], by = bias[n0+col+1];
                const int row_l = wm + mi*16 + g;
                float* s0 = stage + (size_t)row_l*132 + col;
                float* s1 = stage + (size_t)(row_l+8)*132 + col;
                s0[0] = acc[mi][ni][0] + bx; s0[1] = acc[mi][ni][1] + by;
                s1[0] = acc[mi][ni][2] + bx; s1[1] = acc[mi][ni][3] + by;
            }
        }
        __syncthreads();
        #pragma unroll
        for(int i=0;i<16;i++){
            const int row = wid*16 + i;
            float4 v = *(const float4*)(stage + (size_t)row*132 + lane*4);
            *(float4*)(Cf + (size_t)(m0+row)*N + n0 + lane*4) = v;
        }
        return;
    }

    if (MODE == 2 && n0 >= VOFF){
        __syncthreads();
        float* stage = (float*)smh + wid*2304;
        #pragma unroll
        for(int mi=0; mi<2; mi++){
            #pragma unroll
            for(int ni=0; ni<8; ni++){
                const int cl = ni*8 + 2*t4;
                const int sl = mi*16 + g;
                const float b0 = bias[n0+wn+cl], b1 = bias[n0+wn+cl+1];
                stage[(cl  )*36 + sl  ] = acc[mi][ni][0] + b0;
                stage[(cl+1)*36 + sl  ] = acc[mi][ni][1] + b1;
                stage[(cl  )*36 + sl+8] = acc[mi][ni][2] + b0;
                stage[(cl+1)*36 + sl+8] = acc[mi][ni][3] + b1;
            }
        }
        __syncwarp();
        const int b    = m0 >> 9;
        const int soff = (m0 + wm) & 511;
        #pragma unroll
        for(int t=0; t<8; t++){
            const int unit = lane + t*32;
            const int dr = unit >> 2;
            const int gi = (unit >> 1) & 1;
            const int tt = unit & 1;
            const float* sp = stage + dr*36 + gi*16 + 4*tt;
            uint4 o;
            o.x = h2u(__floats2half2_rn(sp[0],  sp[1]));
            o.y = h2u(__floats2half2_rn(sp[8],  sp[9]));
            o.z = h2u(__floats2half2_rn(sp[2],  sp[3]));
            o.w = h2u(__floats2half2_rn(sp[10], sp[11]));
            *(uint4*)(vT + ((size_t)(b*768 + (n0 - VOFF) + wn + dr))*512
                          + soff + gi*16 + 8*tt) = o;
        }
        return;
    }

    __syncthreads();
    {
        __half* stage = smh;
        #pragma unroll
        for(int mi=0; mi<2; mi++){
            #pragma unroll
            for(int ni=0; ni<8; ni++){
                const int c = n0 + wn + ni*8 + 2*t4;
                const float bx = bias[c], by = bias[c+1];
                float v0 = acc[mi][ni][0] + bx;
                float v1 = acc[mi][ni][1] + by;
                float v2 = acc[mi][ni][2] + bx;
                float v3 = acc[mi][ni][3] + by;
                if (MODE == 1){
                    v0 = gelu_exact(v0); v1 = gelu_exact(v1);
                    v2 = gelu_exact(v2); v3 = gelu_exact(v3);
                }
                if (MODE == 2){
                    // Q also folds log2(e) so attention scores are log2-domain
                    const float sc = (n0 < KOFF) ? 0.125f*LOG2E : 1.0f;
                    v0 *= sc; v1 *= sc; v2 *= sc; v3 *= sc;
                }
                const int row_l = wm + mi*16 + g;
                const int grp   = wn + (ni>>1)*16;
                const int slot  = 2*t4 + (ni & 1);
                ((__half2*)(stage + (size_t)row_l*136 + grp))[slot]
                    = __floats2half2_rn(v0, v1);
                ((__half2*)(stage + (size_t)(row_l+8)*136 + grp))[slot]
                    = __floats2half2_rn(v2, v3);
            }
        }
        __syncthreads();
        #pragma unroll
        for(int i=0;i<8;i++){
            const int row = wid*16 + i*2 + (lane >> 4);
            const int seg = lane & 15;
            uint4 v = *(const uint4*)(stage + (size_t)row*136 + seg*8);
            *(uint4*)(Ch + (size_t)(m0+row)*N + n0 + seg*8) = v;
        }
    }
}

// ---------------- fused flash attention (fp16 mma, log2-domain softmax) -----------
#define FL_SMEM 51200

__global__ __launch_bounds__(256, 2)
void flash_attn(const __half* __restrict__ qkv, const __half* __restrict__ vT,
                const float* __restrict__ mask, __half* __restrict__ ctx)
{
    extern __shared__ __half fh[];
    __half* Qs  = fh;                 // [128][64] swizzled
    __half* Ksm = fh + 8192;          // [2][64][64]
    __half* Vsm = fh + 16384;         // [2][64][64]
    float*  msk = (float*)(fh + 24576);  // [512], pre-scaled by log2(e)

    const int tid  = threadIdx.x;
    const int wid  = tid >> 5;
    const int lane = tid & 31;
    const int g  = lane >> 2;
    const int t4 = lane & 3;
    const int xrh = (g & 3) << 4;
    const int qt = blockIdx.x;
    const int bh = blockIdx.y;
    const int b    = bh / NHD;
    const int head = bh % NHD;

    const __half* Qg = qkv + ((size_t)(b*SS + qt*128))*QKVS + head*DHD;
    const __half* Kg = qkv + ((size_t)(b*SS))*QKVS + KOFF + head*DHD;
    const __half* Vg = vT  + ((size_t)(b*HH + head*DHD))*SS;

    if (tid < 128){
        float4 mv = *(const float4*)(mask + b*SS + tid*4);
        mv.x *= LOG2E; mv.y *= LOG2E; mv.z *= LOG2E; mv.w *= LOG2E;
        *(float4*)(msk + tid*4) = mv;
    }

    #pragma unroll
    for(int i=0;i<4;i++){
        const int c = tid + i*256;
        const int row = c >> 3, k4 = c & 7;
        const int off = (k4*8) ^ ((row & 3) << 4);
        CP_ASYNC16(s2u(Qs + row*64 + off), Qg + (size_t)row*QKVS + k4*8);
    }
    CP_COMMIT();

    auto load_kv = [&](int kt){
        __half* ks = Ksm + (kt&1)*4096;
        __half* vs = Vsm + (kt&1)*4096;
        #pragma unroll
        for(int i=0;i<2;i++){
            const int c = tid + i*256;
            const int row = c >> 3, k4 = c & 7;
            const int off = (k4*8) ^ ((row & 3) << 4);
            CP_ASYNC16(s2u(ks + row*64 + off), Kg + (size_t)(kt*64+row)*QKVS + k4*8);
            CP_ASYNC16(s2u(vs + row*64 + off), Vg + (size_t)row*SS + kt*64 + k4*8);
        }
        CP_COMMIT();
    };
    load_kv(0);
    load_kv(1);

    float ctxa[8][4];
    #pragma unroll
    for(int dt=0;dt<8;dt++)
        #pragma unroll
        for(int r=0;r<4;r++) ctxa[dt][r]=0.f;
    float m0=-1e30f, m1=-1e30f, l0=0.f, l1=0.f;

    const __half* qb = Qs + (wid*16 + g)*64;

    for(int kt=0; kt<8; kt++){
        if (kt < 7) CP_WAIT(1); else CP_WAIT(0);
        __syncthreads();

        const __half* ks = Ksm + (kt&1)*4096;
        const __half* vs = Vsm + (kt&1)*4096;

        float sacc[8][4];
        #pragma unroll
        for(int nt=0;nt<8;nt++)
            #pragma unroll
            for(int r=0;r<4;r++) sacc[nt][r]=0.f;

        #pragma unroll
        for(int ks2=0; ks2<4; ks2++){
            const int kw = (ks2*16) ^ xrh;
            uint32_t a[4];
            uint2 lo = *(const uint2*)(qb + kw + t4*4);
            uint2 hi = *(const uint2*)(qb + 8*64 + kw + t4*4);
            a[0] = lo.x; a[2] = lo.y;
            a[1] = hi.x; a[3] = hi.y;
            #pragma unroll
            for(int nt=0; nt<8; nt++){
                uint2 bv = *(const uint2*)(ks + (nt*8+g)*64 + kw + t4*4);
                uint32_t br[2] = { bv.x, bv.y };
                mma_f16(sacc[nt], a, br);
            }
        }

        float r0 = -1e30f, r1 = -1e30f;
        #pragma unroll
        for(int nt=0; nt<8; nt++){
            const float mk0 = msk[kt*64 + nt*8 + 2*t4];
            const float mk1 = msk[kt*64 + nt*8 + 2*t4 + 1];
            sacc[nt][0] += mk0; sacc[nt][1] += mk1;
            sacc[nt][2] += mk0; sacc[nt][3] += mk1;
            r0 = fmaxf(r0, fmaxf(sacc[nt][0], sacc[nt][1]));
            r1 = fmaxf(r1, fmaxf(sacc[nt][2], sacc[nt][3]));
        }
        r0 = fmaxf(r0, __shfl_xor_sync(0xffffffffu, r0, 1));
        r0 = fmaxf(r0, __shfl_xor_sync(0xffffffffu, r0, 2));
        r1 = fmaxf(r1, __shfl_xor_sync(0xffffffffu, r1, 1));
        r1 = fmaxf(r1, __shfl_xor_sync(0xffffffffu, r1, 2));

        const float mn0 = fmaxf(m0, r0);
        const float mn1 = fmaxf(m1, r1);
        const float al0 = ex2(m0 - mn0);
        const float al1 = ex2(m1 - mn1);
        m0 = mn0; m1 = mn1;
        l0 *= al0; l1 *= al1;
        #pragma unroll
        for(int dt=0; dt<8; dt++){
            ctxa[dt][0] *= al0; ctxa[dt][1] *= al0;
            ctxa[dt][2] *= al1; ctxa[dt][3] *= al1;
        }

        __half2 ph[8][2];
        float ps0 = 0.f, ps1 = 0.f;
        #pragma unroll
        for(int nt=0; nt<8; nt++){
            float e0 = ex2(sacc[nt][0]-mn0);
            float e1 = ex2(sacc[nt][1]-mn0);
            float e2 = ex2(sacc[nt][2]-mn1);
            float e3 = ex2(sacc[nt][3]-mn1);
            ph[nt][0] = __floats2half2_rn(e0, e1);
            ph[nt][1] = __floats2half2_rn(e2, e3);
            float2 f0 = __half22float2(ph[nt][0]);
            float2 f1 = __half22float2(ph[nt][1]);
            ps0 += f0.x + f0.y;
            ps1 += f1.x + f1.y;
        }
        l0 += ps0; l1 += ps1;

        #pragma unroll
        for(int ks2=0; ks2<4; ks2++){
            uint32_t a[4] = { h2u(ph[2*ks2][0]),   h2u(ph[2*ks2][1]),
                              h2u(ph[2*ks2+1][0]), h2u(ph[2*ks2+1][1]) };
            const int kw = (ks2*16) ^ xrh;
            #pragma unroll
            for(int dt=0; dt<8; dt++){
                uint2 bv = *(const uint2*)(vs + (dt*8+g)*64 + kw + t4*4);
                uint32_t br[2] = { bv.x, bv.y };
                mma_f16(ctxa[dt], a, br);
            }
        }
        __syncthreads();
        if (kt + 2 < 8) load_kv(kt + 2);
    }

    l0 += __shfl_xor_sync(0xffffffffu, l0, 1);
    l0 += __shfl_xor_sync(0xffffffffu, l0, 2);
    l1 += __shfl_xor_sync(0xffffffffu, l1, 1);
    l1 += __shfl_xor_sync(0xffffffffu, l1, 2);
    const float inv0 = 1.0f / l0;
    const float inv1 = 1.0f / l1;

    const int token0 = b*SS + qt*128 + wid*16 + g;
    __half* o0 = ctx + (size_t)token0*HH + head*DHD;
    __half* o1 = o0 + (size_t)8*HH;
    #pragma unroll
    for(int dt=0; dt<8; dt++){
        const int pi = (dt>>1)*8 + 2*t4 + (dt&1);
        ((__half2*)o0)[pi] = __floats2half2_rn(ctxa[dt][0]*inv0, ctxa[dt][1]*inv0);
        ((__half2*)o1)[pi] = __floats2half2_rn(ctxa[dt][2]*inv1, ctxa[dt][3]*inv1);
    }
}

// ---------------- add residual + layernorm (2 tokens/block) -----------------------
__global__ __launch_bounds__(192)
void add_layernorm_dual(const float* __restrict__ x, const float* __restrict__ res,
                        const float* __restrict__ g, const float* __restrict__ bta,
                        float* __restrict__ out, __half* __restrict__ outp)
{
    const int t   = threadIdx.x;
    const int sub = t / 96;
    const int tl  = t - sub*96;
    const int tok = blockIdx.x*2 + sub;
    const int c8  = tl * 8;
    const float* xp = x   + (size_t)tok*HH + c8;
    const float* rp = res + (size_t)tok*HH + c8;

    float4 xa = *(const float4*)xp;
    float4 xb = *(const float4*)(xp + 4);
    float4 ra = *(const float4*)rp;
    float4 rb = *(const float4*)(rp + 4);
    float v[8];
    v[0]=xa.x+ra.x; v[1]=xa.y+ra.y; v[2]=xa.z+ra.z; v[3]=xa.w+ra.w;
    v[4]=xb.x+rb.x; v[5]=xb.y+rb.y; v[6]=xb.z+rb.z; v[7]=xb.w+rb.w;

    float s = 0.f, sq = 0.f;
    #pragma unroll
    for(int i=0;i<8;i++){ s += v[i]; sq += v[i]*v[i]; }

    __shared__ float rs[6], rq[6];
    float ws = warpSum(s), wq = warpSum(sq);
    const int warp = t >> 5, lane = t & 31;
    if(lane==0){ rs[warp]=ws; rq[warp]=wq; }
    __syncthreads();
    const int w0 = sub*3;
    const float tS = rs[w0]+rs[w0+1]+rs[w0+2];
    const float tQ = rq[w0]+rq[w0+1]+rq[w0+2];
    const float mean = tS * (1.0f/768.0f);
    const float var  = tQ * (1.0f/768.0f) - mean*mean;
    const float inv  = rsqrtf(var + 1e-12f);

    const float4 ga = *(const float4*)(g + c8);
    const float4 gb = *(const float4*)(g + c8 + 4);
    const float4 ba = *(const float4*)(bta + c8);
    const float4 bb = *(const float4*)(bta + c8 + 4);
    float o[8];
    o[0] = (v[0]-mean)*inv*ga.x + ba.x;
    o[1] = (v[1]-mean)*inv*ga.y + ba.y;
    o[2] = (v[2]-mean)*inv*ga.z + ba.z;
    o[3] = (v[3]-mean)*inv*ga.w + ba.w;
    o[4] = (v[4]-mean)*inv*gb.x + bb.x;
    o[5] = (v[5]-mean)*inv*gb.y + bb.y;
    o[6] = (v[6]-mean)*inv*gb.z + bb.z;
    o[7] = (v[7]-mean)*inv*gb.w + bb.w;

    float* op = out + (size_t)tok*HH + c8;
    *(float4*)op       = make_float4(o[0], o[1], o[2], o[3]);
    *(float4*)(op + 4) = make_float4(o[4], o[5], o[6], o[7]);

    const int off = tl & 1;
    __half2* pp = (__half2*)(outp + (size_t)tok*HH + (c8 & ~15));
    #pragma unroll
    for(int j=0;j<4;j++)
        pp[off + 2*j] = __floats2half2_rn(o[2*j], o[2*j+1]);
}

// ---------------- launch -------------------------------------------------------------
extern "C" void kernel_launch(void* const* d_in, const int* in_sizes, int n_in,
                              void* d_out, int out_size)
{
    const float* hs   = (const float*)d_in[0];
    const float* mask = (const float*)d_in[1];
    const float* Wq   = (const float*)d_in[2];
    const float* bq   = (const float*)d_in[3];
    const float* Wk   = (const float*)d_in[4];
    const float* bk   = (const float*)d_in[5];
    const float* Wv   = (const float*)d_in[6];
    const float* bv   = (const float*)d_in[7];
    const float* Wo   = (const float*)d_in[8];
    const float* bo   = (const float*)d_in[9];
    const float* g1   = (const float*)d_in[10];
    const float* b1   = (const float*)d_in[11];
    const float* Wi   = (const float*)d_in[12];
    const float* bi   = (const float*)d_in[13];
    const float* Wo2  = (const float*)d_in[14];
    const float* bo2  = (const float*)d_in[15];
    const float* g2   = (const float*)d_in[16];
    const float* b2   = (const float*)d_in[17];

    float *h, *attn, *tmp, *bqkv;
    __half *qkv, *vT, *ctx, *inter, *rA, *wqkvT, *woT, *wiT, *wo2T;
    cudaGetSymbolAddress((void**)&h,      g_h);
    cudaGetSymbolAddress((void**)&qkv,    g_qkv);
    cudaGetSymbolAddress((void**)&vT,     g_vT);
    cudaGetSymbolAddress((void**)&ctx,    g_ctx);
    cudaGetSymbolAddress((void**)&attn,   g_attn);
    cudaGetSymbolAddress((void**)&tmp,    g_tmp);
    cudaGetSymbolAddress((void**)&inter,  g_inter);
    cudaGetSymbolAddress((void**)&rA,     g_round);
    cudaGetSymbolAddress((void**)&wqkvT,  g_wqkvT);
    cudaGetSymbolAddress((void**)&bqkv,   g_bqkv);
    cudaGetSymbolAddress((void**)&woT,    g_woT);
    cudaGetSymbolAddress((void**)&wiT,    g_wiT);
    cudaGetSymbolAddress((void**)&wo2T,   g_wo2T);

    cudaFuncSetAttribute(mma_gemm<0>, cudaFuncAttributeMaxDynamicSharedMemorySize, SM128);
    cudaFuncSetAttribute(mma_gemm<1>, cudaFuncAttributeMaxDynamicSharedMemorySize, SM128);
    cudaFuncSetAttribute(mma_gemm<2>, cudaFuncAttributeMaxDynamicSharedMemorySize, SM128);
    cudaFuncSetAttribute(flash_attn,  cudaFuncAttributeMaxDynamicSharedMemorySize, FL_SMEM);

    const int nH = M_TOK*HH;

    concat_bias<<<(LAYERS*HH+255)/256, 256>>>(bq, bk, bv, bqkv);
    round_perm_h<<<(nH/2+255)/256, 256>>>(rA, hs, nH/2);
    trans_qkv<<<dim3(HH/32, HH/32, 3*LAYERS), 256>>>(Wq, Wk, Wv, wqkvT);

    dim3 gQKV(QKVS/128, M_TOK/128);   // (18, 32)
    dim3 gFF1(FFD/128,  M_TOK/128);   // (24, 32)
    dim3 gOUT(HH/128,   M_TOK/128);   // (6, 32)

    for(int l=0; l<LAYERS; l++){
        const float* lbo  = bo  + (size_t)l*HH;
        const float* lbi  = bi  + (size_t)l*FFD;
        const float* lbo2 = bo2 + (size_t)l*HH;
        const float* lg1  = g1  + (size_t)l*HH;
        const float* lb1  = b1  + (size_t)l*HH;
        const float* lg2  = g2  + (size_t)l*HH;
        const float* lb2  = b2  + (size_t)l*HH;
        const float* lres = (l == 0) ? hs : h;

        mma_gemm<2><<<gQKV, 256, SM128>>>(
            rA, wqkvT + (size_t)l*QKVS*HH, bqkv + (size_t)l*QKVS,
            qkv, nullptr, vT, QKVS, HH);

        if (l == 0){
            trans_wo <<<dim3(HH/32, HH/32, LAYERS),  256>>>(Wo, woT);
            trans_wi <<<dim3(FFD/32, HH/32, LAYERS), 256>>>(Wi, wiT);
            trans_wo2<<<dim3(HH/32, FFD/32, LAYERS), 256>>>(Wo2, wo2T);
        }

        flash_attn<<<dim3(4, BB*NHD), 256, FL_SMEM>>>(qkv, vT, mask, ctx);

        mma_gemm<0><<<gOUT, 256, SM128>>>(
            ctx, woT + (size_t)l*HH*HH, lbo, nullptr, tmp, nullptr, HH, HH);
        add_layernorm_dual<<<M_TOK/2, 192>>>(tmp, lres, lg1, lb1, attn, rA);

        mma_gemm<1><<<gFF1, 256, SM128>>>(
            rA, wiT + (size_t)l*HH*FFD, lbi, inter, nullptr, nullptr, FFD, HH);
        mma_gemm<0><<<gOUT, 256, SM128>>>(
            inter, wo2T + (size_t)l*FFD*HH, lbo2, nullptr, tmp, nullptr, HH, FFD);
        add_layernorm_dual<<<M_TOK/2, 192>>>(tmp, attn, lg2, lb2,
                                             (l==LAYERS-1) ? (float*)d_out : h, rA);
    }
}

// round 17
// speedup vs baseline: 1.0684x; 1.0684x over previous
#include <cuda_runtime.h>
#include <cuda_fp16.h>
#include <math.h>
#include <stdint.h>

#define LAYERS 12
#define BB 8
#define SS 512
#define HH 768
#define NHD 12
#define DHD 64
#define FFD 3072
#define M_TOK (BB*SS)   // 4096
#define QKVS 2304
#define KOFF 768
#define VOFF 1536
#define LOG2E 1.4426950408889634f

// ---------------- scratch -----------------------------------------------------
__device__ float  g_h[M_TOK*HH];
__device__ __half g_qkv[M_TOK*QKVS];
__device__ __half g_vT[BB*NHD*DHD*SS];      // [bh*64+d][s], s pair-permuted
__device__ __half g_ctx[M_TOK*HH];
__device__ float  g_attn[M_TOK*HH];
__device__ float  g_tmp[M_TOK*HH];
__device__ __half g_round[M_TOK*HH];
__device__ __half g_inter[M_TOK*FFD];

__device__ __half g_wqkvT[LAYERS*QKVS*HH];
__device__ float  g_bqkv [LAYERS*QKVS];
__device__ __half g_woT  [LAYERS*HH*HH];
__device__ __half g_wiT  [LAYERS*HH*FFD];
__device__ __half g_wo2T [LAYERS*FFD*HH];

// ---------------- helpers -----------------------------------------------------
__inline__ __device__ float warpSum(float v){
    #pragma unroll
    for(int o=16;o;o>>=1) v += __shfl_xor_sync(0xffffffffu, v, o);
    return v;
}
__device__ __forceinline__ float gelu_exact(float x){
    return 0.5f * x * (1.0f + erff(x * 0.70710678118654752440f));
}
__device__ __forceinline__ uint32_t s2u(const void* p){
    uint32_t a;
    asm("{ .reg .u64 t; cvta.to.shared.u64 t, %1; cvt.u32.u64 %0, t; }" : "=r"(a) : "l"(p));
    return a;
}
__device__ __forceinline__ int permk(int j){ return ((j&3)<<1) | (j>>2); }
__device__ __forceinline__ uint32_t h2u(__half2 h){ return *(uint32_t*)&h; }
__device__ __forceinline__ float ex2(float x){
    float r; asm("ex2.approx.f32 %0, %1;" : "=f"(r) : "f"(x)); return r;
}

#define CP_ASYNC16(dst, src) \
    asm volatile("cp.async.cg.shared.global [%0], [%1], 16;" :: "r"(dst), "l"(src))
#define CP_COMMIT() asm volatile("cp.async.commit_group;")
#define CP_WAIT(N)  asm volatile("cp.async.wait_group %0;" :: "n"(N) : "memory")

// fp16 mma, fp32 accumulate
__device__ __forceinline__ void mma_f16(float* d, const uint32_t* a, const uint32_t* b){
    asm volatile(
        "mma.sync.aligned.m16n8k16.row.col.f32.f16.f16.f32 "
        "{%0,%1,%2,%3}, {%4,%5,%6,%7}, {%8,%9}, {%0,%1,%2,%3};"
        : "+f"(d[0]), "+f"(d[1]), "+f"(d[2]), "+f"(d[3])
        : "r"(a[0]), "r"(a[1]), "r"(a[2]), "r"(a[3]), "r"(b[0]), "r"(b[1]));
}

// ---------------- elementwise ---------------------------------------------------
__global__ void round_perm_h(__half* __restrict__ dst, const float* __restrict__ src, int nPairs){
    int i = blockIdx.x*blockDim.x + threadIdx.x;
    if(i < nPairs){
        int grp = i >> 3, q = i & 7;
        ((__half2*)dst)[grp*8 + permk(q)] = __floats2half2_rn(src[2*i], src[2*i+1]);
    }
}
__global__ void concat_bias(const float* __restrict__ bq, const float* __restrict__ bk,
                            const float* __restrict__ bv, float* __restrict__ bqkv){
    int i = blockIdx.x*blockDim.x + threadIdx.x;
    if(i < LAYERS*HH){
        int l = i / HH, c = i % HH;
        bqkv[(size_t)l*QKVS + c]        = bq[i];
        bqkv[(size_t)l*QKVS + KOFF + c] = bk[i];
        bqkv[(size_t)l*QKVS + VOFF + c] = bv[i];
    }
}

// ---- transpose + rn-half + pair-perm: src [K][N] float -> dst [rowOff+n][K] half
__device__ __forceinline__ void trans_tile(
    const float* __restrict__ src, __half* __restrict__ dst,
    int K, int N, int rowOff, int n0, int k0)
{
    __shared__ float ts[32][33];
    const int t = threadIdx.x;                 // 256
    {
        const int r = t >> 3, c4 = t & 7;
        float4 v = *(const float4*)(src + (size_t)(k0+r)*N + n0 + c4*4);
        ts[r][c4*4+0] = v.x; ts[r][c4*4+1] = v.y;
        ts[r][c4*4+2] = v.z; ts[r][c4*4+3] = v.w;
    }
    __syncthreads();
    if(t < 128){
        const int nr  = t >> 2;
        const int grp = (t >> 1) & 1;
        const int h8  = t & 1;
        __align__(16) __half tmp[8];
        #pragma unroll
        for(int i=0;i<4;i++){
            const int s = h8*4 + i;
            const int q = ((s & 1) << 2) | (s >> 1);  // inverse of permk
            tmp[2*i]   = __float2half_rn(ts[grp*16 + 2*q    ][nr]);
            tmp[2*i+1] = __float2half_rn(ts[grp*16 + 2*q + 1][nr]);
        }
        *(uint4*)(dst + (size_t)(rowOff + n0 + nr)*K + k0 + grp*16 + h8*8)
            = *(uint4*)tmp;
    }
}

__global__ void trans_qkv(const float* __restrict__ Wq, const float* __restrict__ Wk,
                          const float* __restrict__ Wv, __half* __restrict__ wqkvT){
    const int z = blockIdx.z, l = z / 3, w = z % 3;
    const float* src = (w==0) ? Wq : (w==1) ? Wk : Wv;
    trans_tile(src + (size_t)l*HH*HH, wqkvT + (size_t)l*QKVS*HH,
               HH, HH, w*KOFF, blockIdx.x*32, blockIdx.y*32);
}
__global__ void trans_wo(const float* __restrict__ Wo, __half* __restrict__ woT){
    trans_tile(Wo + (size_t)blockIdx.z*HH*HH, woT + (size_t)blockIdx.z*HH*HH,
               HH, HH, 0, blockIdx.x*32, blockIdx.y*32);
}
__global__ void trans_wi(const float* __restrict__ Wi, __half* __restrict__ wiT){
    trans_tile(Wi + (size_t)blockIdx.z*HH*FFD, wiT + (size_t)blockIdx.z*HH*FFD,
               HH, FFD, 0, blockIdx.x*32, blockIdx.y*32);
}
__global__ void trans_wo2(const float* __restrict__ Wo2, __half* __restrict__ wo2T){
    trans_tile(Wo2 + (size_t)blockIdx.z*FFD*HH, wo2T + (size_t)blockIdx.z*FFD*HH,
               FFD, HH, 0, blockIdx.x*32, blockIdx.y*32);
}

// ---------------- FP16 GEMM, 128x128 tile, BK=64, 3-stage, 2 CTA/SM --------------
// MODE 1: gelu + half pair-perm (FF1). MODE 2: QKV epilogue (half qkv + vT).
#define BKH 64
#define GSTAGES 3
#define SM128 (GSTAGES*(128+128)*BKH*2)    // 98304 -> 2 CTA/SM
#define SM64  (GSTAGES*(128+ 64)*BKH*2)    // 73728 -> 3 CTA/SM

template<int MODE>
__global__ __launch_bounds__(256, 2)
void mma_gemm(const __half* __restrict__ A, const __half* __restrict__ Wt,
              const float* __restrict__ bias, __half* __restrict__ Ch,
              __half* __restrict__ vT, int N, int K)
{
    extern __shared__ __half smh[];
    __half* Asm = smh;
    __half* Wsm = smh + GSTAGES*128*BKH;

    const int tid  = threadIdx.x;
    const int wid  = tid >> 5;
    const int lane = tid & 31;
    const int m0 = blockIdx.y * 128;
    const int n0 = blockIdx.x * 128;
    const int wm = (wid >> 1) * 32;
    const int wn = (wid & 1) * 64;
    const int g  = lane >> 2;
    const int t4 = lane & 3;
    const int xrh = (g & 3) << 4;
    const int KT = K / BKH;

    const __half* Ag = A  + (size_t)m0 * K;
    const __half* Wg = Wt + (size_t)n0 * K;

    auto load_tile = [&](int t){
        const int s = t % GSTAGES;
        __half* as = Asm + s*128*BKH;
        __half* ws = Wsm + s*128*BKH;
        #pragma unroll
        for(int l=0;l<4;l++){
            const int c = tid + l*256;
            const int row = c >> 3, k4 = c & 7;
            const int off = (k4*8) ^ ((row & 3) << 4);
            CP_ASYNC16(s2u(as + row*BKH + off), Ag + (size_t)row*K + t*BKH + k4*8);
        }
        #pragma unroll
        for(int l=0;l<4;l++){
            const int c = tid + l*256;
            const int row = c >> 3, k4 = c & 7;
            const int off = (k4*8) ^ ((row & 3) << 4);
            CP_ASYNC16(s2u(ws + row*BKH + off), Wg + (size_t)row*K + t*BKH + k4*8);
        }
        CP_COMMIT();
    };

    float acc[2][8][4];
    #pragma unroll
    for(int mi=0;mi<2;mi++)
        #pragma unroll
        for(int ni=0;ni<8;ni++)
            #pragma unroll
            for(int r=0;r<4;r++) acc[mi][ni][r] = 0.f;

    load_tile(0);
    load_tile(1);

    for(int t=0; t<KT; t++){
        if (t == KT-1) CP_WAIT(0); else CP_WAIT(1);
        __syncthreads();
        if (t+2 < KT) load_tile(t+2);

        const __half* as = Asm + (t % GSTAGES)*128*BKH;
        const __half* ws = Wsm + (t % GSTAGES)*128*BKH;

        #pragma unroll
        for(int ks=0; ks<BKH/16; ks++){
            const int kw = (ks*16) ^ xrh;
            uint32_t a[2][4], b[8][2];
            #pragma unroll
            for(int mi=0; mi<2; mi++){
                const __half* ap = as + (wm + mi*16 + g)*BKH + kw + t4*4;
                uint2 lo = *(const uint2*)ap;
                uint2 hi = *(const uint2*)(ap + 8*BKH);
                a[mi][0] = lo.x; a[mi][2] = lo.y;
                a[mi][1] = hi.x; a[mi][3] = hi.y;
            }
            #pragma unroll
            for(int ni=0; ni<8; ni++){
                uint2 bv = *(const uint2*)(ws + (wn + ni*8 + g)*BKH + kw + t4*4);
                b[ni][0] = bv.x; b[ni][1] = bv.y;
            }
            #pragma unroll
            for(int mi=0; mi<2; mi++)
                #pragma unroll
                for(int ni=0; ni<8; ni++)
                    mma_f16(acc[mi][ni], a[mi], b[ni]);
        }
    }

    if (MODE == 2 && n0 >= VOFF){
        __syncthreads();
        float* stage = (float*)smh + wid*2304;
        #pragma unroll
        for(int mi=0; mi<2; mi++){
            #pragma unroll
            for(int ni=0; ni<8; ni++){
                const int cl = ni*8 + 2*t4;
                const int sl = mi*16 + g;
                const float b0 = bias[n0+wn+cl], b1 = bias[n0+wn+cl+1];
                stage[(cl  )*36 + sl  ] = acc[mi][ni][0] + b0;
                stage[(cl+1)*36 + sl  ] = acc[mi][ni][1] + b1;
                stage[(cl  )*36 + sl+8] = acc[mi][ni][2] + b0;
                stage[(cl+1)*36 + sl+8] = acc[mi][ni][3] + b1;
            }
        }
        __syncwarp();
        const int b    = m0 >> 9;
        const int soff = (m0 + wm) & 511;
        #pragma unroll
        for(int t=0; t<8; t++){
            const int unit = lane + t*32;
            const int dr = unit >> 2;
            const int gi = (unit >> 1) & 1;
            const int tt = unit & 1;
            const float* sp = stage + dr*36 + gi*16 + 4*tt;
            uint4 o;
            o.x = h2u(__floats2half2_rn(sp[0],  sp[1]));
            o.y = h2u(__floats2half2_rn(sp[8],  sp[9]));
            o.z = h2u(__floats2half2_rn(sp[2],  sp[3]));
            o.w = h2u(__floats2half2_rn(sp[10], sp[11]));
            *(uint4*)(vT + ((size_t)(b*768 + (n0 - VOFF) + wn + dr))*512
                          + soff + gi*16 + 8*tt) = o;
        }
        return;
    }

    __syncthreads();
    {
        __half* stage = smh;
        #pragma unroll
        for(int mi=0; mi<2; mi++){
            #pragma unroll
            for(int ni=0; ni<8; ni++){
                const int c = n0 + wn + ni*8 + 2*t4;
                const float bx = bias[c], by = bias[c+1];
                float v0 = acc[mi][ni][0] + bx;
                float v1 = acc[mi][ni][1] + by;
                float v2 = acc[mi][ni][2] + bx;
                float v3 = acc[mi][ni][3] + by;
                if (MODE == 1){
                    v0 = gelu_exact(v0); v1 = gelu_exact(v1);
                    v2 = gelu_exact(v2); v3 = gelu_exact(v3);
                }
                if (MODE == 2){
                    // Q also folds log2(e) so attention scores are log2-domain
                    const float sc = (n0 < KOFF) ? 0.125f*LOG2E : 1.0f;
                    v0 *= sc; v1 *= sc; v2 *= sc; v3 *= sc;
                }
                const int row_l = wm + mi*16 + g;
                const int grp   = wn + (ni>>1)*16;
                const int slot  = 2*t4 + (ni & 1);
                ((__half2*)(stage + (size_t)row_l*136 + grp))[slot]
                    = __floats2half2_rn(v0, v1);
                ((__half2*)(stage + (size_t)(row_l+8)*136 + grp))[slot]
                    = __floats2half2_rn(v2, v3);
            }
        }
        __syncthreads();
        #pragma unroll
        for(int i=0;i<8;i++){
            const int row = wid*16 + i*2 + (lane >> 4);
            const int seg = lane & 15;
            uint4 v = *(const uint4*)(stage + (size_t)row*136 + seg*8);
            *(uint4*)(Ch + (size_t)(m0+row)*N + n0 + seg*8) = v;
        }
    }
}

// ---------------- FP16 GEMM, 128x64 tile, BK=64, 3-stage, 3 CTA/SM ---------------
__global__ __launch_bounds__(128, 3)
void mma_gemm64(const __half* __restrict__ A, const __half* __restrict__ Wt,
                const float* __restrict__ bias, float* __restrict__ C,
                int N, int K)
{
    extern __shared__ __half smh[];
    __half* Asm = smh;
    __half* Wsm = smh + GSTAGES*128*BKH;

    const int tid  = threadIdx.x;
    const int wid  = tid >> 5;
    const int lane = tid & 31;
    const int m0 = blockIdx.y * 128;
    const int n0 = blockIdx.x * 64;
    const int wm = wid * 32;
    const int g  = lane >> 2;
    const int t4 = lane & 3;
    const int xrh = (g & 3) << 4;
    const int KT = K / BKH;

    const __half* Ag = A  + (size_t)m0 * K;
    const __half* Wg = Wt + (size_t)n0 * K;

    auto load_tile = [&](int t){
        const int s = t % GSTAGES;
        __half* as = Asm + s*128*BKH;
        __half* ws = Wsm + s*64*BKH;
        #pragma unroll
        for(int l=0;l<8;l++){
            const int c = tid + l*128;
            const int row = c >> 3, k4 = c & 7;
            const int off = (k4*8) ^ ((row & 3) << 4);
            CP_ASYNC16(s2u(as + row*BKH + off), Ag + (size_t)row*K + t*BKH + k4*8);
        }
        #pragma unroll
        for(int l=0;l<4;l++){
            const int c = tid + l*128;
            const int row = c >> 3, k4 = c & 7;
            const int off = (k4*8) ^ ((row & 3) << 4);
            CP_ASYNC16(s2u(ws + row*BKH + off), Wg + (size_t)row*K + t*BKH + k4*8);
        }
        CP_COMMIT();
    };

    float acc[2][8][4];
    #pragma unroll
    for(int mi=0;mi<2;mi++)
        #pragma unroll
        for(int ni=0;ni<8;ni++)
            #pragma unroll
            for(int r=0;r<4;r++) acc[mi][ni][r] = 0.f;

    load_tile(0);
    load_tile(1);

    for(int t=0; t<KT; t++){
        if (t == KT-1) CP_WAIT(0); else CP_WAIT(1);
        __syncthreads();
        if (t+2 < KT) load_tile(t+2);

        const __half* as = Asm + (t % GSTAGES)*128*BKH;
        const __half* ws = Wsm + (t % GSTAGES)*64*BKH;

        #pragma unroll
        for(int ks=0; ks<BKH/16; ks++){
            const int kw = (ks*16) ^ xrh;
            uint32_t a[2][4], b[8][2];
            #pragma unroll
            for(int mi=0; mi<2; mi++){
                const __half* ap = as + (wm + mi*16 + g)*BKH + kw + t4*4;
                uint2 lo = *(const uint2*)ap;
                uint2 hi = *(const uint2*)(ap + 8*BKH);
                a[mi][0] = lo.x; a[mi][2] = lo.y;
                a[mi][1] = hi.x; a[mi][3] = hi.y;
            }
            #pragma unroll
            for(int ni=0; ni<8; ni++){
                uint2 bv = *(const uint2*)(ws + (ni*8 + g)*BKH + kw + t4*4);
                b[ni][0] = bv.x; b[ni][1] = bv.y;
            }
            #pragma unroll
            for(int mi=0; mi<2; mi++)
                #pragma unroll
                for(int ni=0; ni<8; ni++)
                    mma_f16(acc[mi][ni], a[mi], b[ni]);
        }
    }

    __syncthreads();
    {
        float* stage = (float*)smh;
        #pragma unroll
        for(int mi=0; mi<2; mi++){
            #pragma unroll
            for(int ni=0; ni<8; ni++){
                const int col = ni*8 + 2*t4;
                const float bx = bias[n0+col], by = bias[n0+col+1];
                const int row_l = wm + mi*16 + g;
                float* s0 = stage + (size_t)row_l*76 + col;
                float* s1 = stage + (size_t)(row_l+8)*76 + col;
                s0[0] = acc[mi][ni][0] + bx; s0[1] = acc[mi][ni][1] + by;
                s1[0] = acc[mi][ni][2] + bx; s1[1] = acc[mi][ni][3] + by;
            }
        }
        __syncthreads();
        #pragma unroll
        for(int i=0;i<16;i++){
            const int row = wid*32 + i*2 + (lane >> 4);
            const int seg = lane & 15;
            float4 v = *(const float4*)(stage + (size_t)row*76 + seg*4);
            *(float4*)(C + (size_t)(m0+row)*N + n0 + seg*4) = v;
        }
    }
}

// ---------------- fused flash attention (fp16 mma, log2-domain softmax) -----------
#define FL_SMEM 51200

__global__ __launch_bounds__(256, 2)
void flash_attn(const __half* __restrict__ qkv, const __half* __restrict__ vT,
                const float* __restrict__ mask, __half* __restrict__ ctx)
{
    extern __shared__ __half fh[];
    __half* Qs  = fh;                 // [128][64] swizzled
    __half* Ksm = fh + 8192;          // [2][64][64]
    __half* Vsm = fh + 16384;         // [2][64][64]
    float*  msk = (float*)(fh + 24576);  // [512], pre-scaled by log2(e)

    const int tid  = threadIdx.x;
    const int wid  = tid >> 5;
    const int lane = tid & 31;
    const int g  = lane >> 2;
    const int t4 = lane & 3;
    const int xrh = (g & 3) << 4;
    const int qt = blockIdx.x;
    const int bh = blockIdx.y;
    const int b    = bh / NHD;
    const int head = bh % NHD;

    const __half* Qg = qkv + ((size_t)(b*SS + qt*128))*QKVS + head*DHD;
    const __half* Kg = qkv + ((size_t)(b*SS))*QKVS + KOFF + head*DHD;
    const __half* Vg = vT  + ((size_t)(b*HH + head*DHD))*SS;

    if (tid < 128){
        float4 mv = *(const float4*)(mask + b*SS + tid*4);
        mv.x *= LOG2E; mv.y *= LOG2E; mv.z *= LOG2E; mv.w *= LOG2E;
        *(float4*)(msk + tid*4) = mv;
    }

    #pragma unroll
    for(int i=0;i<4;i++){
        const int c = tid + i*256;
        const int row = c >> 3, k4 = c & 7;
        const int off = (k4*8) ^ ((row & 3) << 4);
        CP_ASYNC16(s2u(Qs + row*64 + off), Qg + (size_t)row*QKVS + k4*8);
    }
    CP_COMMIT();

    auto load_kv = [&](int kt){
        __half* ks = Ksm + (kt&1)*4096;
        __half* vs = Vsm + (kt&1)*4096;
        #pragma unroll
        for(int i=0;i<2;i++){
            const int c = tid + i*256;
            const int row = c >> 3, k4 = c & 7;
            const int off = (k4*8) ^ ((row & 3) << 4);
            CP_ASYNC16(s2u(ks + row*64 + off), Kg + (size_t)(kt*64+row)*QKVS + k4*8);
            CP_ASYNC16(s2u(vs + row*64 + off), Vg + (size_t)row*SS + kt*64 + k4*8);
        }
        CP_COMMIT();
    };
    load_kv(0);
    load_kv(1);

    float ctxa[8][4];
    #pragma unroll
    for(int dt=0;dt<8;dt++)
        #pragma unroll
        for(int r=0;r<4;r++) ctxa[dt][r]=0.f;
    float m0=-1e30f, m1=-1e30f, l0=0.f, l1=0.f;

    const __half* qb = Qs + (wid*16 + g)*64;

    for(int kt=0; kt<8; kt++){
        if (kt < 7) CP_WAIT(1); else CP_WAIT(0);
        __syncthreads();

        const __half* ks = Ksm + (kt&1)*4096;
        const __half* vs = Vsm + (kt&1)*4096;

        float sacc[8][4];
        #pragma unroll
        for(int nt=0;nt<8;nt++)
            #pragma unroll
            for(int r=0;r<4;r++) sacc[nt][r]=0.f;

        #pragma unroll
        for(int ks2=0; ks2<4; ks2++){
            const int kw = (ks2*16) ^ xrh;
            uint32_t a[4];
            uint2 lo = *(const uint2*)(qb + kw + t4*4);
            uint2 hi = *(const uint2*)(qb + 8*64 + kw + t4*4);
            a[0] = lo.x; a[2] = lo.y;
            a[1] = hi.x; a[3] = hi.y;
            #pragma unroll
            for(int nt=0; nt<8; nt++){
                uint2 bv = *(const uint2*)(ks + (nt*8+g)*64 + kw + t4*4);
                uint32_t br[2] = { bv.x, bv.y };
                mma_f16(sacc[nt], a, br);
            }
        }

        float r0 = -1e30f, r1 = -1e30f;
        #pragma unroll
        for(int nt=0; nt<8; nt++){
            const float mk0 = msk[kt*64 + nt*8 + 2*t4];
            const float mk1 = msk[kt*64 + nt*8 + 2*t4 + 1];
            sacc[nt][0] += mk0; sacc[nt][1] += mk1;
            sacc[nt][2] += mk0; sacc[nt][3] += mk1;
            r0 = fmaxf(r0, fmaxf(sacc[nt][0], sacc[nt][1]));
            r1 = fmaxf(r1, fmaxf(sacc[nt][2], sacc[nt][3]));
        }
        r0 = fmaxf(r0, __shfl_xor_sync(0xffffffffu, r0, 1));
        r0 = fmaxf(r0, __shfl_xor_sync(0xffffffffu, r0, 2));
        r1 = fmaxf(r1, __shfl_xor_sync(0xffffffffu, r1, 1));
        r1 = fmaxf(r1, __shfl_xor_sync(0xffffffffu, r1, 2));

        const float mn0 = fmaxf(m0, r0);
        const float mn1 = fmaxf(m1, r1);
        const float al0 = ex2(m0 - mn0);
        const float al1 = ex2(m1 - mn1);
        m0 = mn0; m1 = mn1;
        l0 *= al0; l1 *= al1;
        #pragma unroll
        for(int dt=0; dt<8; dt++){
            ctxa[dt][0] *= al0; ctxa[dt][1] *= al0;
            ctxa[dt][2] *= al1; ctxa[dt][3] *= al1;
        }

        __half2 ph[8][2];
        float ps0 = 0.f, ps1 = 0.f;
        #pragma unroll
        for(int nt=0; nt<8; nt++){
            float e0 = ex2(sacc[nt][0]-mn0);
            float e1 = ex2(sacc[nt][1]-mn0);
            float e2 = ex2(sacc[nt][2]-mn1);
            float e3 = ex2(sacc[nt][3]-mn1);
            ph[nt][0] = __floats2half2_rn(e0, e1);
            ph[nt][1] = __floats2half2_rn(e2, e3);
            float2 f0 = __half22float2(ph[nt][0]);
            float2 f1 = __half22float2(ph[nt][1]);
            ps0 += f0.x + f0.y;
            ps1 += f1.x + f1.y;
        }
        l0 += ps0; l1 += ps1;

        #pragma unroll
        for(int ks2=0; ks2<4; ks2++){
            uint32_t a[4] = { h2u(ph[2*ks2][0]),   h2u(ph[2*ks2][1]),
                              h2u(ph[2*ks2+1][0]), h2u(ph[2*ks2+1][1]) };
            const int kw = (ks2*16) ^ xrh;
            #pragma unroll
            for(int dt=0; dt<8; dt++){
                uint2 bv = *(const uint2*)(vs + (dt*8+g)*64 + kw + t4*4);
                uint32_t br[2] = { bv.x, bv.y };
                mma_f16(ctxa[dt], a, br);
            }
        }
        __syncthreads();
        if (kt + 2 < 8) load_kv(kt + 2);
    }

    l0 += __shfl_xor_sync(0xffffffffu, l0, 1);
    l0 += __shfl_xor_sync(0xffffffffu, l0, 2);
    l1 += __shfl_xor_sync(0xffffffffu, l1, 1);
    l1 += __shfl_xor_sync(0xffffffffu, l1, 2);
    const float inv0 = 1.0f / l0;
    const float inv1 = 1.0f / l1;

    const int token0 = b*SS + qt*128 + wid*16 + g;
    __half* o0 = ctx + (size_t)token0*HH + head*DHD;
    __half* o1 = o0 + (size_t)8*HH;
    #pragma unroll
    for(int dt=0; dt<8; dt++){
        const int pi = (dt>>1)*8 + 2*t4 + (dt&1);
        ((__half2*)o0)[pi] = __floats2half2_rn(ctxa[dt][0]*inv0, ctxa[dt][1]*inv0);
        ((__half2*)o1)[pi] = __floats2half2_rn(ctxa[dt][2]*inv1, ctxa[dt][3]*inv1);
    }
}

// ---------------- add residual + layernorm (2 tokens/block) -----------------------
__global__ __launch_bounds__(192)
void add_layernorm_dual(const float* __restrict__ x, const float* __restrict__ res,
                        const float* __restrict__ g, const float* __restrict__ bta,
                        float* __restrict__ out, __half* __restrict__ outp)
{
    const int t   = threadIdx.x;
    const int sub = t / 96;
    const int tl  = t - sub*96;
    const int tok = blockIdx.x*2 + sub;
    const int c8  = tl * 8;
    const float* xp = x   + (size_t)tok*HH + c8;
    const float* rp = res + (size_t)tok*HH + c8;

    float4 xa = *(const float4*)xp;
    float4 xb = *(const float4*)(xp + 4);
    float4 ra = *(const float4*)rp;
    float4 rb = *(const float4*)(rp + 4);
    float v[8];
    v[0]=xa.x+ra.x; v[1]=xa.y+ra.y; v[2]=xa.z+ra.z; v[3]=xa.w+ra.w;
    v[4]=xb.x+rb.x; v[5]=xb.y+rb.y; v[6]=xb.z+rb.z; v[7]=xb.w+rb.w;

    float s = 0.f, sq = 0.f;
    #pragma unroll
    for(int i=0;i<8;i++){ s += v[i]; sq += v[i]*v[i]; }

    __shared__ float rs[6], rq[6];
    float ws = warpSum(s), wq = warpSum(sq);
    const int warp = t >> 5, lane = t & 31;
    if(lane==0){ rs[warp]=ws; rq[warp]=wq; }
    __syncthreads();
    const int w0 = sub*3;
    const float tS = rs[w0]+rs[w0+1]+rs[w0+2];
    const float tQ = rq[w0]+rq[w0+1]+rq[w0+2];
    const float mean = tS * (1.0f/768.0f);
    const float var  = tQ * (1.0f/768.0f) - mean*mean;
    const float inv  = rsqrtf(var + 1e-12f);

    const float4 ga = *(const float4*)(g + c8);
    const float4 gb = *(const float4*)(g + c8 + 4);
    const float4 ba = *(const float4*)(bta + c8);
    const float4 bb = *(const float4*)(bta + c8 + 4);
    float o[8];
    o[0] = (v[0]-mean)*inv*ga.x + ba.x;
    o[1] = (v[1]-mean)*inv*ga.y + ba.y;
    o[2] = (v[2]-mean)*inv*ga.z + ba.z;
    o[3] = (v[3]-mean)*inv*ga.w + ba.w;
    o[4] = (v[4]-mean)*inv*gb.x + bb.x;
    o[5] = (v[5]-mean)*inv*gb.y + bb.y;
    o[6] = (v[6]-mean)*inv*gb.z + bb.z;
    o[7] = (v[7]-mean)*inv*gb.w + bb.w;

    float* op = out + (size_t)tok*HH + c8;
    *(float4*)op       = make_float4(o[0], o[1], o[2], o[3]);
    *(float4*)(op + 4) = make_float4(o[4], o[5], o[6], o[7]);

    const int off = tl & 1;
    __half2* pp = (__half2*)(outp + (size_t)tok*HH + (c8 & ~15));
    #pragma unroll
    for(int j=0;j<4;j++)
        pp[off + 2*j] = __floats2half2_rn(o[2*j], o[2*j+1]);
}

// ---------------- launch -------------------------------------------------------------
extern "C" void kernel_launch(void* const* d_in, const int* in_sizes, int n_in,
                              void* d_out, int out_size)
{
    const float* hs   = (const float*)d_in[0];
    const float* mask = (const float*)d_in[1];
    const float* Wq   = (const float*)d_in[2];
    const float* bq   = (const float*)d_in[3];
    const float* Wk   = (const float*)d_in[4];
    const float* bk   = (const float*)d_in[5];
    const float* Wv   = (const float*)d_in[6];
    const float* bv   = (const float*)d_in[7];
    const float* Wo   = (const float*)d_in[8];
    const float* bo   = (const float*)d_in[9];
    const float* g1   = (const float*)d_in[10];
    const float* b1   = (const float*)d_in[11];
    const float* Wi   = (const float*)d_in[12];
    const float* bi   = (const float*)d_in[13];
    const float* Wo2  = (const float*)d_in[14];
    const float* bo2  = (const float*)d_in[15];
    const float* g2   = (const float*)d_in[16];
    const float* b2   = (const float*)d_in[17];

    float *h, *attn, *tmp, *bqkv;
    __half *qkv, *vT, *ctx, *inter, *rA, *wqkvT, *woT, *wiT, *wo2T;
    cudaGetSymbolAddress((void**)&h,      g_h);
    cudaGetSymbolAddress((void**)&qkv,    g_qkv);
    cudaGetSymbolAddress((void**)&vT,     g_vT);
    cudaGetSymbolAddress((void**)&ctx,    g_ctx);
    cudaGetSymbolAddress((void**)&attn,   g_attn);
    cudaGetSymbolAddress((void**)&tmp,    g_tmp);
    cudaGetSymbolAddress((void**)&inter,  g_inter);
    cudaGetSymbolAddress((void**)&rA,     g_round);
    cudaGetSymbolAddress((void**)&wqkvT,  g_wqkvT);
    cudaGetSymbolAddress((void**)&bqkv,   g_bqkv);
    cudaGetSymbolAddress((void**)&woT,    g_woT);
    cudaGetSymbolAddress((void**)&wiT,    g_wiT);
    cudaGetSymbolAddress((void**)&wo2T,   g_wo2T);

    cudaFuncSetAttribute(mma_gemm<2>, cudaFuncAttributeMaxDynamicSharedMemorySize, SM128);
    cudaFuncSetAttribute(mma_gemm<1>, cudaFuncAttributeMaxDynamicSharedMemorySize, SM128);
    cudaFuncSetAttribute(mma_gemm64,  cudaFuncAttributeMaxDynamicSharedMemorySize, SM64);
    cudaFuncSetAttribute(flash_attn,  cudaFuncAttributeMaxDynamicSharedMemorySize, FL_SMEM);

    const int nH = M_TOK*HH;

    concat_bias<<<(LAYERS*HH+255)/256, 256>>>(bq, bk, bv, bqkv);
    round_perm_h<<<(nH/2+255)/256, 256>>>(rA, hs, nH/2);
    trans_qkv<<<dim3(HH/32, HH/32, 3*LAYERS), 256>>>(Wq, Wk, Wv, wqkvT);

    dim3 gQKV(QKVS/128, M_TOK/128);   // (18, 32)
    dim3 gFF1(FFD/128,  M_TOK/128);   // (24, 32)
    dim3 gN64(HH/64,    M_TOK/128);   // (12, 32)

    for(int l=0; l<LAYERS; l++){
        const float* lbo  = bo  + (size_t)l*HH;
        const float* lbi  = bi  + (size_t)l*FFD;
        const float* lbo2 = bo2 + (size_t)l*HH;
        const float* lg1  = g1  + (size_t)l*HH;
        const float* lb1  = b1  + (size_t)l*HH;
        const float* lg2  = g2  + (size_t)l*HH;
        const float* lb2  = b2  + (size_t)l*HH;
        const float* lres = (l == 0) ? hs : h;

        mma_gemm<2><<<gQKV, 256, SM128>>>(
            rA, wqkvT + (size_t)l*QKVS*HH, bqkv + (size_t)l*QKVS,
            qkv, vT, QKVS, HH);

        if (l == 0){
            trans_wo <<<dim3(HH/32, HH/32, LAYERS),  256>>>(Wo, woT);
            trans_wi <<<dim3(FFD/32, HH/32, LAYERS), 256>>>(Wi, wiT);
            trans_wo2<<<dim3(HH/32, FFD/32, LAYERS), 256>>>(Wo2, wo2T);
        }

        flash_attn<<<dim3(4, BB*NHD), 256, FL_SMEM>>>(qkv, vT, mask, ctx);

        mma_gemm64<<<gN64, 128, SM64>>>(
            ctx, woT + (size_t)l*HH*HH, lbo, tmp, HH, HH);
        add_layernorm_dual<<<M_TOK/2, 192>>>(tmp, lres, lg1, lb1, attn, rA);

        mma_gemm<1><<<gFF1, 256, SM128>>>(
            rA, wiT + (size_t)l*HH*FFD, lbi, inter, nullptr, FFD, HH);
        mma_gemm64<<<gN64, 128, SM64>>>(
            inter, wo2T + (size_t)l*FFD*HH, lbo2, tmp, HH, FFD);
        add_layernorm_dual<<<M_TOK/2, 192>>>(tmp, attn, lg2, lb2,
                                             (l==LAYERS-1) ? (float*)d_out : h, rA);
    }
}